// round 2
// baseline (speedup 1.0000x reference)
#include <cuda_runtime.h>
#include <cuda_fp16.h>
#include <cstdint>
#include <cstddef>

// ===================== problem constants =====================
constexpr int Bb = 8, Tt = 2048, Dd = 2048;
constexpr int Mrows = Bb * Tt;            // 16384
constexpr long long DDll = (long long)Dd * Dd;
constexpr int DD = Dd * Dd;               // 4194304

// ===================== scratch (device globals, no alloc) =====================
__device__ __half g_h0[(size_t)Mrows * Dd];   // ak -> wkv*r -> kcm
__device__ __half g_h1[(size_t)Mrows * Dd];   // av -> cm kmix
__device__ __half g_h2[(size_t)Mrows * Dd];   // ar -> cm rmix
__device__ __half g_h3[(size_t)Mrows * Dd];   // r  -> rcm
__device__ float  g_k [(size_t)Mrows * Dd];   // scan k (fp32)
__device__ float  g_v [(size_t)Mrows * Dd];   // scan v (fp32)
__device__ float  g_x1[(size_t)Mrows * Dd];   // x + att
__device__ __half g_Wh[(size_t)7 * DD];       // fp16 weights
__device__ float  g_mu[Mrows];
__device__ float  g_rs[Mrows];

// ===================== small helpers =====================
__device__ __forceinline__ uint32_t smem_u32(const void* p) {
    uint32_t a;
    asm("{ .reg .u64 t; cvta.to.shared.u64 t, %1; cvt.u32.u64 %0, t; }" : "=r"(a) : "l"(p));
    return a;
}
template <int N>
__device__ __forceinline__ void cp_wait() {
    asm volatile("cp.async.wait_group %0;" :: "n"(N));
}
__device__ __forceinline__ void cp_commit() {
    asm volatile("cp.async.commit_group;" ::: "memory");
}
__device__ __forceinline__ void cp_async16(uint32_t saddr, const void* gaddr) {
    asm volatile("cp.async.cg.shared.global [%0], [%1], 16;" :: "r"(saddr), "l"(gaddr));
}
__device__ __forceinline__ void ldm_x4(uint32_t* r, uint32_t addr) {
    asm volatile("ldmatrix.sync.aligned.m8n8.x4.shared.b16 {%0,%1,%2,%3}, [%4];"
                 : "=r"(r[0]), "=r"(r[1]), "=r"(r[2]), "=r"(r[3]) : "r"(addr));
}
__device__ __forceinline__ void mma16816(float* c, const uint32_t* a, uint32_t b0, uint32_t b1) {
    asm volatile(
        "mma.sync.aligned.m16n8k16.row.col.f32.f16.f16.f32 "
        "{%0,%1,%2,%3}, {%4,%5,%6,%7}, {%8,%9}, {%0,%1,%2,%3};"
        : "+f"(c[0]), "+f"(c[1]), "+f"(c[2]), "+f"(c[3])
        : "r"(a[0]), "r"(a[1]), "r"(a[2]), "r"(a[3]), "r"(b0), "r"(b1));
}
__device__ __forceinline__ float sigmoidf_(float x) { return 1.0f / (1.0f + __expf(-x)); }

// ===================== GEMM: C[m,n] = sum_k A[m,k] * W[n,k] =====================
// A: [16384,2048] f16 row-major, W: [2048,2048] f16 row-major, BM=BN=128, BK=64.
// EPI: 0 store f32, 1 store f16, 2 sigmoid->f16, 3 relu^2->f16,
//      4 +bias[n]+res -> f32, 5 res + half(rmul)*acc -> f32
template <int EPI>
__global__ __launch_bounds__(256, 2)
void gemm_k(const __half* __restrict__ A, const __half* __restrict__ W,
            float* __restrict__ outf, __half* __restrict__ outh,
            const float* __restrict__ bias, const float* __restrict__ res,
            const __half* __restrict__ rmul)
{
    extern __shared__ uint8_t sm[];
    const int tid  = threadIdx.x;
    const int m0   = blockIdx.y * 128;
    const int n0   = blockIdx.x * 128;
    const int warp = tid >> 5, lane = tid & 31;
    const int wm   = (warp & 3) * 32;
    const int wn   = (warp >> 2) * 64;

    const uint32_t sbase = smem_u32(sm);   // stage s: A at s*32768, B at +16384

    auto load_stage = [&](int s, int k0) {
        uint32_t abase = sbase + s * 32768;
        uint32_t bbase = abase + 16384;
#pragma unroll
        for (int i = 0; i < 4; i++) {
            int idx = tid + i * 256;
            int row = idx >> 3, kb = idx & 7;
            const __half* ga = A + (size_t)(m0 + row) * 2048 + k0 + kb * 8;
            cp_async16(abase + row * 128 + ((kb ^ (row & 7)) << 4), ga);
            const __half* gb = W + (size_t)(n0 + row) * 2048 + k0 + kb * 8;
            cp_async16(bbase + row * 128 + ((kb ^ (row & 7)) << 4), gb);
        }
        cp_commit();
    };

    float acc[2][8][4];
#pragma unroll
    for (int i = 0; i < 2; i++)
#pragma unroll
        for (int j = 0; j < 8; j++)
#pragma unroll
            for (int q = 0; q < 4; q++) acc[i][j][q] = 0.f;

    load_stage(0, 0);

    for (int ks = 0; ks < 32; ks++) {
        if (ks + 1 < 32) { load_stage((ks + 1) & 1, (ks + 1) * 64); cp_wait<1>(); }
        else             { cp_wait<0>(); }
        __syncthreads();
        uint32_t abase = sbase + (ks & 1) * 32768;
        uint32_t bbase = abase + 16384;
#pragma unroll
        for (int k16 = 0; k16 < 4; k16++) {
            const int chunk = k16 * 2 + ((lane >> 4) & 1);
            uint32_t afr[2][4];
#pragma unroll
            for (int mi = 0; mi < 2; mi++) {
                int row = wm + mi * 16 + (lane & 15);
                ldm_x4(afr[mi], abase + row * 128 + ((chunk ^ (row & 7)) << 4));
            }
#pragma unroll
            for (int ni = 0; ni < 4; ni++) {
                int row = wn + ni * 16 + (lane & 15);
                uint32_t bfr[4];
                ldm_x4(bfr, bbase + row * 128 + ((chunk ^ (row & 7)) << 4));
#pragma unroll
                for (int mi = 0; mi < 2; mi++) {
                    mma16816(acc[mi][2 * ni],     afr[mi], bfr[0], bfr[2]);
                    mma16816(acc[mi][2 * ni + 1], afr[mi], bfr[1], bfr[3]);
                }
            }
        }
        __syncthreads();
    }

    // ---------------- epilogue ----------------
#pragma unroll
    for (int mi = 0; mi < 2; mi++) {
#pragma unroll
        for (int nj = 0; nj < 8; nj++) {
            int r0 = m0 + wm + mi * 16 + (lane >> 2);
            int cc = n0 + wn + nj * 8 + ((lane & 3) << 1);
            size_t i0 = ((size_t)r0 << 11) + cc;
            size_t i1 = i0 + ((size_t)8 << 11);
            const float* d = acc[mi][nj];
            if (EPI == 0) {
                *(float2*)(outf + i0) = make_float2(d[0], d[1]);
                *(float2*)(outf + i1) = make_float2(d[2], d[3]);
            } else if (EPI == 1) {
                *(__half2*)(outh + i0) = __floats2half2_rn(d[0], d[1]);
                *(__half2*)(outh + i1) = __floats2half2_rn(d[2], d[3]);
            } else if (EPI == 2) {
                *(__half2*)(outh + i0) = __floats2half2_rn(sigmoidf_(d[0]), sigmoidf_(d[1]));
                *(__half2*)(outh + i1) = __floats2half2_rn(sigmoidf_(d[2]), sigmoidf_(d[3]));
            } else if (EPI == 3) {
                float t0v = fmaxf(d[0], 0.f), t1v = fmaxf(d[1], 0.f);
                float t2v = fmaxf(d[2], 0.f), t3v = fmaxf(d[3], 0.f);
                *(__half2*)(outh + i0) = __floats2half2_rn(t0v * t0v, t1v * t1v);
                *(__half2*)(outh + i1) = __floats2half2_rn(t2v * t2v, t3v * t3v);
            } else if (EPI == 4) {
                float b0v = bias[cc], b1v = bias[cc + 1];
                float2 x0 = *(const float2*)(res + i0);
                float2 x1v = *(const float2*)(res + i1);
                *(float2*)(outf + i0) = make_float2(d[0] + b0v + x0.x,  d[1] + b1v + x0.y);
                *(float2*)(outf + i1) = make_float2(d[2] + b0v + x1v.x, d[3] + b1v + x1v.y);
            } else { // 5
                __half2 rh0 = *(const __half2*)(rmul + i0);
                __half2 rh1 = *(const __half2*)(rmul + i1);
                float2 rf0 = __half22float2(rh0), rf1 = __half22float2(rh1);
                float2 x0 = *(const float2*)(res + i0);
                float2 x1v = *(const float2*)(res + i1);
                *(float2*)(outf + i0) = make_float2(x0.x + rf0.x * d[0],  x0.y + rf0.y * d[1]);
                *(float2*)(outf + i1) = make_float2(x1v.x + rf1.x * d[2], x1v.y + rf1.y * d[3]);
            }
        }
    }
}

// ===================== weight fp32 -> fp16 =====================
__global__ void wconv_k(const float* __restrict__ w0, const float* __restrict__ w1,
                        const float* __restrict__ w2, const float* __restrict__ w3,
                        const float* __restrict__ w4, const float* __restrict__ w5,
                        const float* __restrict__ w6)
{
    int i4 = blockIdx.x * 256 + threadIdx.x;      // total 7*DD/4
    int seg = i4 / (DD / 4);
    int off4 = (i4 - seg * (DD / 4)) << 2;
    const float* src;
    switch (seg) {
        case 0: src = w0; break; case 1: src = w1; break; case 2: src = w2; break;
        case 3: src = w3; break; case 4: src = w4; break; case 5: src = w5; break;
        default: src = w6; break;
    }
    float4 v = *(const float4*)(src + off4);
    __half2* dst = (__half2*)(g_Wh + (size_t)seg * DD + off4);
    dst[0] = __floats2half2_rn(v.x, v.y);
    dst[1] = __floats2half2_rn(v.z, v.w);
}

// ===================== LayerNorm row stats =====================
__global__ void ln_stats_k(const float* __restrict__ xin)
{
    __shared__ float sbuf[16];
    int row = blockIdx.x;
    const float* xr = xin + ((size_t)row << 11);
    float s = 0.f, s2 = 0.f;
    for (int i = threadIdx.x; i < 2048; i += 256) { float v = xr[i]; s += v; s2 += v * v; }
#pragma unroll
    for (int o = 16; o; o >>= 1) { s += __shfl_xor_sync(~0u, s, o); s2 += __shfl_xor_sync(~0u, s2, o); }
    int w = threadIdx.x >> 5;
    if ((threadIdx.x & 31) == 0) { sbuf[w] = s; sbuf[8 + w] = s2; }
    __syncthreads();
    if (threadIdx.x == 0) {
        float S = 0.f, S2 = 0.f;
#pragma unroll
        for (int i = 0; i < 8; i++) { S += sbuf[i]; S2 += sbuf[8 + i]; }
        float m = S * (1.f / 2048.f);
        float var = S2 * (1.f / 2048.f) - m * m;
        g_mu[row] = m;
        g_rs[row] = rsqrtf(var + 1e-5f);
    }
}

// ===================== time-mix prep (LN1 + shift + mixes) =====================
__global__ void tm_prep_k(const float* __restrict__ xin,
                          const float* __restrict__ lnw, const float* __restrict__ lnb,
                          const float* __restrict__ mk, const float* __restrict__ mv,
                          const float* __restrict__ mr)
{
    int i4 = blockIdx.x * 256 + threadIdx.x;   // total Mrows*Dd/4
    int row = i4 >> 9;
    int c4 = (i4 & 511) << 2;
    int t = row & 2047;
    size_t gi = ((size_t)row << 11) + c4;

    float xa[4]; *(float4*)xa = *(const float4*)(xin + gi);
    float m = g_mu[row], r_ = g_rs[row];
    float xsa[4] = {0.f, 0.f, 0.f, 0.f};
    float ms = 0.f, rss = 0.f;
    if (t) { *(float4*)xsa = *(const float4*)(xin + gi - 2048); ms = g_mu[row - 1]; rss = g_rs[row - 1]; }

    float ak[4], av[4], ar[4];
#pragma unroll
    for (int j = 0; j < 4; j++) {
        int c = c4 + j;
        float lw = lnw[c], lb = lnb[c];
        float lx  = (xa[j] - m) * r_ * lw + lb;
        float lxs = t ? (xsa[j] - ms) * rss * lw + lb : 0.f;
        float k_ = mk[c]; ak[j] = lx * k_ + lxs * (1.f - k_);
        float v_ = mv[c]; av[j] = lx * v_ + lxs * (1.f - v_);
        float q_ = mr[c]; ar[j] = sigmoidf_(lx * q_ + lxs * (1.f - q_));
    }
    *(__half2*)(g_h0 + gi)     = __floats2half2_rn(ak[0], ak[1]);
    *(__half2*)(g_h0 + gi + 2) = __floats2half2_rn(ak[2], ak[3]);
    *(__half2*)(g_h1 + gi)     = __floats2half2_rn(av[0], av[1]);
    *(__half2*)(g_h1 + gi + 2) = __floats2half2_rn(av[2], av[3]);
    *(__half2*)(g_h2 + gi)     = __floats2half2_rn(ar[0], ar[1]);
    *(__half2*)(g_h2 + gi + 2) = __floats2half2_rn(ar[2], ar[3]);
}

// ===================== channel-mix prep (LN2 + shift + mixes) =====================
__global__ void cm_prep_k(const float* __restrict__ xin,
                          const float* __restrict__ lnw, const float* __restrict__ lnb,
                          const float* __restrict__ mk, const float* __restrict__ mr)
{
    int i4 = blockIdx.x * 256 + threadIdx.x;
    int row = i4 >> 9;
    int c4 = (i4 & 511) << 2;
    int t = row & 2047;
    size_t gi = ((size_t)row << 11) + c4;

    float xa[4]; *(float4*)xa = *(const float4*)(xin + gi);
    float m = g_mu[row], r_ = g_rs[row];
    float xsa[4] = {0.f, 0.f, 0.f, 0.f};
    float ms = 0.f, rss = 0.f;
    if (t) { *(float4*)xsa = *(const float4*)(xin + gi - 2048); ms = g_mu[row - 1]; rss = g_rs[row - 1]; }

    float ak[4], ar[4];
#pragma unroll
    for (int j = 0; j < 4; j++) {
        int c = c4 + j;
        float lw = lnw[c], lb = lnb[c];
        float lx  = (xa[j] - m) * r_ * lw + lb;
        float lxs = t ? (xsa[j] - ms) * rss * lw + lb : 0.f;
        float k_ = mk[c]; ak[j] = lx * k_ + lxs * (1.f - k_);
        float q_ = mr[c]; ar[j] = lx * q_ + lxs * (1.f - q_);
    }
    *(__half2*)(g_h1 + gi)     = __floats2half2_rn(ak[0], ak[1]);
    *(__half2*)(g_h1 + gi + 2) = __floats2half2_rn(ak[2], ak[3]);
    *(__half2*)(g_h2 + gi)     = __floats2half2_rn(ar[0], ar[1]);
    *(__half2*)(g_h2 + gi + 2) = __floats2half2_rn(ar[2], ar[3]);
}

// ===================== chunked parallel WKV scan =====================
// chunks of 128 outputs, 64-step warmup from zero state (decay < 1e-28: exact to fp32)
__global__ void scan_k(const float* __restrict__ u, const float* __restrict__ w)
{
    int gidx = blockIdx.x * 256 + threadIdx.x;   // B * 16 * 2048 total
    int c = gidx & 2047;
    int bc = gidx >> 11;
    int chunk = bc & 15, b = bc >> 4;
    float uu = u[c], ww = w[c];
    int cs = chunk << 7;
    int t0 = cs - 64; if (t0 < 0) t0 = 0;

    const float* kp = g_k + (((size_t)(b * 2048 + t0)) << 11) + c;
    const float* vp = g_v + (((size_t)(b * 2048 + t0)) << 11) + c;
    float a = 0.f, bsum = 0.f;
    for (int t = t0; t < cs; ++t) {
        float kt = *kp, vt = *vp; kp += 2048; vp += 2048;
        float q = fmaxf(uu + kt, ww);
        float e1 = __expf(-ww - q);
        float e2 = __expf(uu + kt - q);
        a = fmaf(e1, a, e2 * vt);
        bsum = fmaf(e1, bsum, e2);
    }
    const __half* rp = g_h3 + (((size_t)(b * 2048 + cs)) << 11) + c;
    __half* op = g_h0 + (((size_t)(b * 2048 + cs)) << 11) + c;
    for (int t = 0; t < 128; ++t) {
        float kt = *kp, vt = *vp; kp += 2048; vp += 2048;
        float q = fmaxf(uu + kt, ww);
        float e1 = __expf(-ww - q);
        float e2 = __expf(uu + kt - q);
        a = fmaf(e1, a, e2 * vt);
        bsum = fmaf(e1, bsum, e2);
        float rr = __half2float(*rp); rp += 2048;
        *op = __float2half(a / bsum * rr); op += 2048;
    }
}

// ===================== launch =====================
extern "C" void kernel_launch(void* const* d_in, const int* in_sizes, int n_in,
                              void* d_out, int out_size)
{
    const float* x     = (const float*)d_in[0];
    const float* ln1w  = (const float*)d_in[1];
    const float* ln1b  = (const float*)d_in[2];
    const float* ln2w  = (const float*)d_in[3];
    const float* ln2b  = (const float*)d_in[4];
    const float* tmu   = (const float*)d_in[5];
    const float* tmw   = (const float*)d_in[6];
    const float* tmk   = (const float*)d_in[7];
    const float* tmv   = (const float*)d_in[8];
    const float* tmr   = (const float*)d_in[9];
    const float* tmWk  = (const float*)d_in[10];
    const float* tmWv  = (const float*)d_in[11];
    const float* tmWr  = (const float*)d_in[12];
    const float* tmWo  = (const float*)d_in[13];
    const float* tmbo  = (const float*)d_in[14];
    const float* cmk   = (const float*)d_in[15];
    const float* cmr   = (const float*)d_in[16];
    const float* cmWk  = (const float*)d_in[17];
    const float* cmWv  = (const float*)d_in[18];
    const float* cmWr  = (const float*)d_in[19];
    float* out = (float*)d_out;

    __half *h0, *h1, *h2, *h3, *wh;
    float *kf, *vf, *x1f;
    cudaGetSymbolAddress((void**)&h0, g_h0);
    cudaGetSymbolAddress((void**)&h1, g_h1);
    cudaGetSymbolAddress((void**)&h2, g_h2);
    cudaGetSymbolAddress((void**)&h3, g_h3);
    cudaGetSymbolAddress((void**)&wh, g_Wh);
    cudaGetSymbolAddress((void**)&kf, g_k);
    cudaGetSymbolAddress((void**)&vf, g_v);
    cudaGetSymbolAddress((void**)&x1f, g_x1);

    const int SMB = 65536;
    cudaFuncSetAttribute(gemm_k<0>, cudaFuncAttributeMaxDynamicSharedMemorySize, SMB);
    cudaFuncSetAttribute(gemm_k<1>, cudaFuncAttributeMaxDynamicSharedMemorySize, SMB);
    cudaFuncSetAttribute(gemm_k<2>, cudaFuncAttributeMaxDynamicSharedMemorySize, SMB);
    cudaFuncSetAttribute(gemm_k<3>, cudaFuncAttributeMaxDynamicSharedMemorySize, SMB);
    cudaFuncSetAttribute(gemm_k<4>, cudaFuncAttributeMaxDynamicSharedMemorySize, SMB);
    cudaFuncSetAttribute(gemm_k<5>, cudaFuncAttributeMaxDynamicSharedMemorySize, SMB);

    dim3 gg(16, 128);   // x: N/128, y: M/128

    // weights fp32 -> fp16 (order: Wk, Wv, Wr, Wo, cmWk, cmWv, cmWr)
    wconv_k<<<(7 * DD / 4) / 256, 256>>>(tmWk, tmWv, tmWr, tmWo, cmWk, cmWv, cmWr);

    // LN1 stats + time-mix prep
    ln_stats_k<<<Mrows, 256>>>(x);
    tm_prep_k<<<(Mrows * (Dd / 4)) / 256, 256>>>(x, ln1w, ln1b, tmk, tmv, tmr);

    // k, v (fp32 for the scan), r = sigmoid(mix) @ Wr.T (fp16)
    gemm_k<0><<<gg, 256, SMB>>>(h0, wh + 0 * DDll, kf, nullptr, nullptr, nullptr, nullptr);
    gemm_k<0><<<gg, 256, SMB>>>(h1, wh + 1 * DDll, vf, nullptr, nullptr, nullptr, nullptr);
    gemm_k<1><<<gg, 256, SMB>>>(h2, wh + 2 * DDll, nullptr, h3, nullptr, nullptr, nullptr);

    // wkv * r  -> h0 (fp16)
    scan_k<<<(Bb * 16 * Dd) / 256, 256>>>(tmu, tmw);

    // x1 = x + (wkv*r) @ Wo.T + bo
    gemm_k<4><<<gg, 256, SMB>>>(h0, wh + 3 * DDll, x1f, nullptr, tmbo, x, nullptr);

    // LN2 stats + channel-mix prep
    ln_stats_k<<<Mrows, 256>>>(x1f);
    cm_prep_k<<<(Mrows * (Dd / 4)) / 256, 256>>>(x1f, ln2w, ln2b, cmk, cmr);

    // kcm = relu(mix @ cmWk.T)^2 (fp16) ; rcm = sigmoid(mix @ cmWr.T) (fp16)
    gemm_k<3><<<gg, 256, SMB>>>(h1, wh + 4 * DDll, nullptr, h0, nullptr, nullptr, nullptr);
    gemm_k<2><<<gg, 256, SMB>>>(h2, wh + 6 * DDll, nullptr, h3, nullptr, nullptr, nullptr);

    // out = x1 + rcm * (kcm @ cmWv.T)
    gemm_k<5><<<gg, 256, SMB>>>(h0, wh + 5 * DDll, out, nullptr, nullptr, x1f, h3);
}

// round 6
// speedup vs baseline: 1.2782x; 1.2782x over previous
#include <cuda_runtime.h>
#include <cuda_fp16.h>
#include <cstdint>
#include <cstddef>

// ===================== problem constants =====================
constexpr int Bb = 8, Tt = 2048, Dd = 2048;
constexpr int Mrows = Bb * Tt;            // 16384
constexpr long long DDll = (long long)Dd * Dd;
constexpr int DD = Dd * Dd;               // 4194304

// ===================== scratch (device globals, no alloc) =====================
__device__ __half g_h0[(size_t)Mrows * Dd];   // ak -> wkv*r -> kcm
__device__ __half g_h1[(size_t)Mrows * Dd];   // av -> cm kmix
__device__ __half g_h2[(size_t)Mrows * Dd];   // ar -> cm rmix
__device__ __half g_h3[(size_t)Mrows * Dd];   // r  -> rcm
__device__ float  g_k [(size_t)Mrows * Dd];   // scan k (fp32)
__device__ float  g_v [(size_t)Mrows * Dd];   // scan v (fp32)
__device__ float  g_x1[(size_t)Mrows * Dd];   // x + att
__device__ __half g_Wh[(size_t)7 * DD];       // fp16 weights
__device__ float  g_mu[Mrows];
__device__ float  g_rs[Mrows];
// tcgen05 self-test state
__device__ uint32_t g_flag;
__device__ __half g_tA[128 * 64];
__device__ __half g_tB[128 * 64];

// ===================== small helpers =====================
__device__ __forceinline__ uint32_t smem_u32(const void* p) {
    uint32_t a;
    asm("{ .reg .u64 t; cvta.to.shared.u64 t, %1; cvt.u32.u64 %0, t; }" : "=r"(a) : "l"(p));
    return a;
}
template <int N>
__device__ __forceinline__ void cp_wait() {
    asm volatile("cp.async.wait_group %0;" :: "n"(N));
}
__device__ __forceinline__ void cp_commit() {
    asm volatile("cp.async.commit_group;" ::: "memory");
}
__device__ __forceinline__ void cp_async16(uint32_t saddr, const void* gaddr) {
    asm volatile("cp.async.cg.shared.global [%0], [%1], 16;" :: "r"(saddr), "l"(gaddr));
}
__device__ __forceinline__ float sigmoidf_(float x) { return 1.0f / (1.0f + __expf(-x)); }

// HMMA primitives (needed on every pass — fallback branch)
__device__ __forceinline__ void ldm_x4(uint32_t* r, uint32_t addr) {
    asm volatile("ldmatrix.sync.aligned.m8n8.x4.shared.b16 {%0,%1,%2,%3}, [%4];"
                 : "=r"(r[0]), "=r"(r[1]), "=r"(r[2]), "=r"(r[3]) : "r"(addr));
}
__device__ __forceinline__ void mma16816(float* c, const uint32_t* a, uint32_t b0, uint32_t b1) {
    asm volatile(
        "mma.sync.aligned.m16n8k16.row.col.f32.f16.f16.f32 "
        "{%0,%1,%2,%3}, {%4,%5,%6,%7}, {%8,%9}, {%0,%1,%2,%3};"
        : "+f"(c[0]), "+f"(c[1]), "+f"(c[2]), "+f"(c[3])
        : "r"(a[0]), "r"(a[1]), "r"(a[2]), "r"(a[3]), "r"(b0), "r"(b1));
}

// cooperative tile load: A rows m0.., B rows n0.., both K-major, row stride 2048 halves
__device__ __forceinline__ void load_tile(uint32_t ab, int tid,
                                          const __half* __restrict__ A,
                                          const __half* __restrict__ W,
                                          int m0, int n0, int k0) {
#pragma unroll
    for (int i = 0; i < 8; i++) {
        int idx = tid + i * 256;            // 0..2047
        int bsel = idx >> 10;               // 0:A 1:B
        int j = idx & 1023;
        int row = j >> 3, kb = j & 7;
        const __half* g = (bsel ? W + ((size_t)(n0 + row) << 11)
                                : A + ((size_t)(m0 + row) << 11)) + k0 + kb * 8;
        cp_async16(ab + bsel * 16384 + row * 128 + ((kb ^ (row & 7)) << 4), g);
    }
    cp_commit();
}

constexpr int GSM = 3 * 32768 + 1024;   // 99328 dyn smem (1KB alignment slack)

#if defined(__CUDA_ARCH_FEAT_SM103_ALL)
// ===================== tcgen05 wrappers (arch-specific pass only) =====================
__device__ __forceinline__ uint32_t elect_one() {
    uint32_t pred;
    asm volatile("{\n .reg .pred p;\n elect.sync _|p, 0xFFFFFFFF;\n selp.b32 %0, 1, 0, p;\n}"
                 : "=r"(pred));
    return pred;
}
#define TCG_ALLOC(sm, n) \
    asm volatile("tcgen05.alloc.cta_group::1.sync.aligned.shared::cta.b32 [%0], %1;" \
                 :: "r"((uint32_t)(sm)), "r"((uint32_t)(n)) : "memory")
#define TCG_RELINQ() \
    asm volatile("tcgen05.relinquish_alloc_permit.cta_group::1.sync.aligned;")
#define TCG_DEALLOC(tm, n) \
    asm volatile("tcgen05.dealloc.cta_group::1.sync.aligned.b32 %0, %1;" :: "r"(tm), "r"((uint32_t)(n)))
#define TCG_COMMIT(mb) \
    asm volatile("tcgen05.commit.cta_group::1.mbarrier::arrive::one.shared::cluster.b64 [%0];" \
                 :: "r"((uint32_t)(mb)) : "memory")
#define TCG_FENCE_AFTER()  asm volatile("tcgen05.fence::after_thread_sync;" ::: "memory")
#define TCG_FENCE_BEFORE() asm volatile("tcgen05.fence::before_thread_sync;" ::: "memory")
#define TCG_WAIT_LD()      asm volatile("tcgen05.wait::ld.sync.aligned;" ::: "memory")
#define FENCE_ASYNC()      asm volatile("fence.proxy.async.shared::cta;" ::: "memory")
#define MBAR_INIT(mb, cnt) \
    asm volatile("mbarrier.init.shared.b64 [%0], %1;" :: "r"((uint32_t)(mb)), "r"((uint32_t)(cnt)) : "memory")
// Bounded wait: never hangs.
#define MBAR_WAIT_B(mb, par) do {                                                 \
    uint32_t _m = (uint32_t)(mb), _p = (uint32_t)(par), _d = 0;                   \
    for (int _i = 0; _i < (1 << 16); ++_i) {                                      \
        asm volatile("{\n .reg .pred p;\n"                                        \
            " mbarrier.try_wait.parity.acquire.cta.shared::cta.b64 p, [%1], %2, 0x989680;\n" \
            " selp.b32 %0, 1, 0, p;\n}" : "=r"(_d) : "r"(_m), "r"(_p) : "memory");\
        if (_d) break;                                                            \
    } } while (0)
#define TCG_LD_X32(r, ta) \
    asm volatile("tcgen05.ld.sync.aligned.32x32b.x32.b32 "                        \
        "{%0, %1, %2, %3, %4, %5, %6, %7, %8, %9, %10, %11, %12, %13, %14, %15, " \
        " %16, %17, %18, %19, %20, %21, %22, %23, %24, %25, %26, %27, %28, %29, %30, %31}, [%32];" \
        : "=r"((r)[0]), "=r"((r)[1]), "=r"((r)[2]), "=r"((r)[3]),                 \
          "=r"((r)[4]), "=r"((r)[5]), "=r"((r)[6]), "=r"((r)[7]),                 \
          "=r"((r)[8]), "=r"((r)[9]), "=r"((r)[10]), "=r"((r)[11]),               \
          "=r"((r)[12]), "=r"((r)[13]), "=r"((r)[14]), "=r"((r)[15]),             \
          "=r"((r)[16]), "=r"((r)[17]), "=r"((r)[18]), "=r"((r)[19]),             \
          "=r"((r)[20]), "=r"((r)[21]), "=r"((r)[22]), "=r"((r)[23]),             \
          "=r"((r)[24]), "=r"((r)[25]), "=r"((r)[26]), "=r"((r)[27]),             \
          "=r"((r)[28]), "=r"((r)[29]), "=r"((r)[30]), "=r"((r)[31])              \
        : "r"(ta))

constexpr uint64_t DESC_BASE_SW128 =
    (uint64_t(2) << 61) | (uint64_t(1) << 46) | (uint64_t(64) << 32) | (uint64_t(1) << 16);
__device__ __forceinline__ uint64_t make_desc(uint32_t addr) {
    return DESC_BASE_SW128 | ((uint64_t)(addr >> 4) & 0x3FFF);
}
__device__ __forceinline__ void mma_f16_ss(uint32_t d_tmem, uint64_t ad, uint64_t bd,
                                           uint32_t idesc, bool acc) {
    uint32_t en = acc ? 1u : 0u;
    asm volatile(
        "{\n .reg .pred p;\n setp.ne.u32 p, %5, 0;\n"
        " tcgen05.mma.cta_group::1.kind::f16 [%0], %1, %2, %3, {%4, %4, %4, %4}, p;\n}"
        :: "r"(d_tmem), "l"(ad), "l"(bd), "r"(idesc), "r"(0u), "r"(en) : "memory");
}
// idesc: dtype F32 (bit4), atype=F16(0), btype=F16(0), N=128 -> (N/8)<<17, M=128 -> (M>>4)<<24
constexpr uint32_t IDESC = (1u << 4) | ((128u / 8) << 17) | ((128u / 16) << 24);
#endif

// ===================== tcgen05 self-test: verified 128x128x64 product =====================
__global__ void __cluster_dims__(1, 1, 1) __launch_bounds__(256, 1) selftest_k()
{
#if defined(__CUDA_ARCH_FEAT_SM103_ALL)
    __shared__ __align__(16) uint8_t ts[2 * 16384 + 1024];
    __shared__ __align__(16) uint32_t s_ctrl[8];
    __shared__ int s_err;
    const int tid = threadIdx.x, warp = tid >> 5, lane = tid & 31;

    // deterministic pattern
    for (int i = tid; i < 128 * 64; i += 256) {
        g_tA[i] = __float2half(0.01f * ((i * 7 + 3) % 31 - 15));
        g_tB[i] = __float2half(0.01f * ((i * 11 + 5) % 29 - 14));
    }
    if (tid == 0) s_err = 0;
    __threadfence();
    __syncthreads();

    const uint32_t ab = (smem_u32(ts) + 1023u) & ~1023u;
    const uint32_t bb = ab + 16384;
    // load both tiles swizzled via cp.async (same protocol as the real GEMM)
#pragma unroll
    for (int i = 0; i < 8; i++) {
        int idx = tid + i * 256;
        int bsel = idx >> 10;
        int j = idx & 1023;
        int row = j >> 3, kb = j & 7;
        const __half* g = (bsel ? g_tB + row * 64 : g_tA + row * 64) + kb * 8;
        cp_async16((bsel ? bb : ab) + row * 128 + ((kb ^ (row & 7)) << 4), g);
    }
    cp_commit();
    cp_wait<0>();
    __syncthreads();
    FENCE_ASYNC();

    const uint32_t ctrl = smem_u32(s_ctrl);
    const uint32_t mbar = ctrl + 16;
    if (warp == 0) { TCG_ALLOC(ctrl, 128); TCG_RELINQ(); }
    if (tid == 0)  { MBAR_INIT(mbar, 1); }
    __syncthreads();
    uint32_t tmem;
    asm volatile("ld.shared.b32 %0, [%1];" : "=r"(tmem) : "r"(ctrl));

    if (warp == 0) {
        TCG_FENCE_AFTER();
        if (elect_one()) {
            uint64_t ad = make_desc(ab), bd = make_desc(bb);
#pragma unroll
            for (int k = 0; k < 4; k++)
                mma_f16_ss(tmem, ad + 2 * k, bd + 2 * k, IDESC, k != 0);
            TCG_COMMIT(mbar);
        }
    }
    MBAR_WAIT_B(mbar, 0);
    TCG_FENCE_AFTER();
    __syncthreads();

    int errs = 0;
    if (warp < 4) {
        int row = warp * 32 + lane;
#pragma unroll 1
        for (int cb = 0; cb < 4; cb++) {
            uint32_t r[32];
            TCG_LD_X32(r, tmem + cb * 32);
            TCG_WAIT_LD();
            for (int c = 0; c < 32; c++) {
                int n = cb * 32 + c;
                float ref = 0.f;
                for (int k = 0; k < 64; k++)
                    ref += __half2float(g_tA[row * 64 + k]) * __half2float(g_tB[n * 64 + k]);
                float got = __uint_as_float(r[c]);
                if (fabsf(got - ref) > 1e-2f * fmaxf(fabsf(ref), 1.f)) errs++;
            }
        }
    }
    if (errs) atomicAdd(&s_err, errs);
    __syncthreads();
    if (tid == 0) g_flag = (s_err == 0) ? 1u : 0u;
    if (warp == 0) TCG_DEALLOC(tmem, 128);
#else
    if (threadIdx.x == 0 && blockIdx.x == 0) g_flag = 0;
#endif
}

// ===================== GEMM: C[m,n] = sum_k A[m,k] * W[n,k] =====================
// Tile 128x128, BK=64, 3 stages. EPI: 0 f32, 1 f16, 2 sigmoid->f16, 3 relu^2->f16,
// 4 +bias[n]+res->f32, 5 res+half(rmul)*acc->f32
template <int EPI>
__global__ void __cluster_dims__(1, 1, 1) __launch_bounds__(256, 2)
gemm_k(const __half* __restrict__ A, const __half* __restrict__ W,
       float* __restrict__ outf, __half* __restrict__ outh,
       const float* __restrict__ bias, const float* __restrict__ res,
       const __half* __restrict__ rmul)
{
    extern __shared__ uint8_t sm[];
    const uint32_t dbase = (smem_u32(sm) + 1023u) & ~1023u;
    const int tid = threadIdx.x, warp = tid >> 5, lane = tid & 31;
    const int m0 = blockIdx.y * 128;
    const int n0 = blockIdx.x * 128;

#if defined(__CUDA_ARCH_FEAT_SM103_ALL)
    const uint32_t use_tcg = g_flag;
    if (use_tcg) {
        // =============== verified tcgen05 path ===============
        __shared__ __align__(16) uint32_t s_ctrl[8];
        const uint32_t ctrl = smem_u32(s_ctrl);
        const uint32_t mbar = ctrl + 16;
        if (warp == 0) { TCG_ALLOC(ctrl, 128); TCG_RELINQ(); }
        if (tid == 0)  { MBAR_INIT(mbar, 1); }
        __syncthreads();
        uint32_t tmem;
        asm volatile("ld.shared.b32 %0, [%1];" : "=r"(tmem) : "r"(ctrl));

        load_tile(dbase, tid, A, W, m0, n0, 0);
        load_tile(dbase + 32768, tid, A, W, m0, n0, 64);
        for (int ks = 0; ks < 32; ++ks) {
            if (ks < 31) cp_wait<1>(); else cp_wait<0>();
            __syncthreads();
            FENCE_ASYNC();                       // publish cp.async writes to async proxy
            if (warp == 0) {
                TCG_FENCE_AFTER();               // order post-barrier tcgen05 vs pre-barrier work
                if (elect_one()) {
                    uint32_t ab = dbase + (ks % 3) * 32768;
                    uint64_t ad = make_desc(ab);
                    uint64_t bd = make_desc(ab + 16384);
#pragma unroll
                    for (int k = 0; k < 4; k++)
                        mma_f16_ss(tmem, ad + 2 * k, bd + 2 * k, IDESC, (ks | k) != 0);
                    TCG_COMMIT(mbar);
                }
            }
            MBAR_WAIT_B(mbar, ks & 1);           // MMA(ks) fully done
            if (ks + 2 < 32) load_tile(dbase + ((ks + 2) % 3) * 32768, tid, A, W, m0, n0, (ks + 2) << 6);
        }
        TCG_FENCE_AFTER();
        __syncthreads();

        // epilogue: TMEM -> smem transpose -> coalesced global
        float* smem_f = reinterpret_cast<float*>(sm + (dbase - smem_u32(sm)));
#pragma unroll 1
        for (int cb = 0; cb < 4; ++cb) {
            if (warp < 4) {
                uint32_t r[32];
                TCG_LD_X32(r, tmem + cb * 32);
                TCG_WAIT_LD();
                int row = (warp << 5) + lane;
#pragma unroll
                for (int c = 0; c < 32; c++) smem_f[row * 33 + c] = __uint_as_float(r[c]);
            }
            __syncthreads();
#pragma unroll
            for (int i = 0; i < 16; i++) {
                int row = warp + (i << 3);
                float v = smem_f[row * 33 + lane];
                int gc = n0 + (cb << 5) + lane;
                size_t gi = ((size_t)(m0 + row) << 11) + gc;
                if (EPI == 0)       outf[gi] = v;
                else if (EPI == 1)  outh[gi] = __float2half(v);
                else if (EPI == 2)  outh[gi] = __float2half(sigmoidf_(v));
                else if (EPI == 3) { float t = fmaxf(v, 0.f); outh[gi] = __float2half(t * t); }
                else if (EPI == 4)  outf[gi] = v + bias[gc] + res[gi];
                else                outf[gi] = res[gi] + __half2float(rmul[gi]) * v;
            }
            __syncthreads();
        }
        if (warp == 0) TCG_DEALLOC(tmem, 128);
        return;
    }
#endif
    // =============== HMMA path (R1-proven structure, 3-stage single-sync) ===============
    {
        const int wm = (warp & 3) * 32;
        const int wn = (warp >> 2) * 64;

        float acc[2][8][4];
#pragma unroll
        for (int i = 0; i < 2; i++)
#pragma unroll
            for (int j = 0; j < 8; j++)
#pragma unroll
                for (int q = 0; q < 4; q++) acc[i][j][q] = 0.f;

        load_tile(dbase, tid, A, W, m0, n0, 0);
        load_tile(dbase + 32768, tid, A, W, m0, n0, 64);

        for (int ks = 0; ks < 32; ++ks) {
            if (ks < 31) cp_wait<1>(); else cp_wait<0>();
            __syncthreads();
            if (ks + 2 < 32) load_tile(dbase + ((ks + 2) % 3) * 32768, tid, A, W, m0, n0, (ks + 2) << 6);

            uint32_t abase = dbase + (ks % 3) * 32768;
            uint32_t bbase = abase + 16384;
#pragma unroll
            for (int k16 = 0; k16 < 4; k16++) {
                const int chunk = k16 * 2 + ((lane >> 4) & 1);
                uint32_t afr[2][4];
#pragma unroll
                for (int mi = 0; mi < 2; mi++) {
                    int row = wm + mi * 16 + (lane & 15);
                    ldm_x4(afr[mi], abase + row * 128 + ((chunk ^ (row & 7)) << 4));
                }
#pragma unroll
                for (int ni = 0; ni < 4; ni++) {
                    int row = wn + ni * 16 + (lane & 15);
                    uint32_t bfr[4];
                    ldm_x4(bfr, bbase + row * 128 + ((chunk ^ (row & 7)) << 4));
#pragma unroll
                    for (int mi = 0; mi < 2; mi++) {
                        mma16816(acc[mi][2 * ni],     afr[mi], bfr[0], bfr[2]);
                        mma16816(acc[mi][2 * ni + 1], afr[mi], bfr[1], bfr[3]);
                    }
                }
            }
        }

#pragma unroll
        for (int mi = 0; mi < 2; mi++) {
#pragma unroll
            for (int nj = 0; nj < 8; nj++) {
                int r0 = m0 + wm + mi * 16 + (lane >> 2);
                int cc = n0 + wn + nj * 8 + ((lane & 3) << 1);
                size_t i0 = ((size_t)r0 << 11) + cc;
                size_t i1 = i0 + ((size_t)8 << 11);
                const float* d = acc[mi][nj];
                if (EPI == 0) {
                    *(float2*)(outf + i0) = make_float2(d[0], d[1]);
                    *(float2*)(outf + i1) = make_float2(d[2], d[3]);
                } else if (EPI == 1) {
                    *(__half2*)(outh + i0) = __floats2half2_rn(d[0], d[1]);
                    *(__half2*)(outh + i1) = __floats2half2_rn(d[2], d[3]);
                } else if (EPI == 2) {
                    *(__half2*)(outh + i0) = __floats2half2_rn(sigmoidf_(d[0]), sigmoidf_(d[1]));
                    *(__half2*)(outh + i1) = __floats2half2_rn(sigmoidf_(d[2]), sigmoidf_(d[3]));
                } else if (EPI == 3) {
                    float t0v = fmaxf(d[0], 0.f), t1v = fmaxf(d[1], 0.f);
                    float t2v = fmaxf(d[2], 0.f), t3v = fmaxf(d[3], 0.f);
                    *(__half2*)(outh + i0) = __floats2half2_rn(t0v * t0v, t1v * t1v);
                    *(__half2*)(outh + i1) = __floats2half2_rn(t2v * t2v, t3v * t3v);
                } else if (EPI == 4) {
                    float b0v = bias[cc], b1v = bias[cc + 1];
                    float2 x0 = *(const float2*)(res + i0);
                    float2 x1v = *(const float2*)(res + i1);
                    *(float2*)(outf + i0) = make_float2(d[0] + b0v + x0.x,  d[1] + b1v + x0.y);
                    *(float2*)(outf + i1) = make_float2(d[2] + b0v + x1v.x, d[3] + b1v + x1v.y);
                } else { // 5
                    __half2 rh0 = *(const __half2*)(rmul + i0);
                    __half2 rh1 = *(const __half2*)(rmul + i1);
                    float2 rf0 = __half22float2(rh0), rf1 = __half22float2(rh1);
                    float2 x0 = *(const float2*)(res + i0);
                    float2 x1v = *(const float2*)(res + i1);
                    *(float2*)(outf + i0) = make_float2(x0.x + rf0.x * d[0],  x0.y + rf0.y * d[1]);
                    *(float2*)(outf + i1) = make_float2(x1v.x + rf1.x * d[2], x1v.y + rf1.y * d[3]);
                }
            }
        }
    }
}

// ===================== weight fp32 -> fp16 =====================
__global__ void wconv_k(const float* __restrict__ w0, const float* __restrict__ w1,
                        const float* __restrict__ w2, const float* __restrict__ w3,
                        const float* __restrict__ w4, const float* __restrict__ w5,
                        const float* __restrict__ w6)
{
    int i4 = blockIdx.x * 256 + threadIdx.x;
    int seg = i4 / (DD / 4);
    int off4 = (i4 - seg * (DD / 4)) << 2;
    const float* src;
    switch (seg) {
        case 0: src = w0; break; case 1: src = w1; break; case 2: src = w2; break;
        case 3: src = w3; break; case 4: src = w4; break; case 5: src = w5; break;
        default: src = w6; break;
    }
    float4 v = *(const float4*)(src + off4);
    __half2* dst = (__half2*)(g_Wh + (size_t)seg * DD + off4);
    dst[0] = __floats2half2_rn(v.x, v.y);
    dst[1] = __floats2half2_rn(v.z, v.w);
}

// ===================== LayerNorm row stats =====================
__global__ void ln_stats_k(const float* __restrict__ xin)
{
    __shared__ float sbuf[16];
    int row = blockIdx.x;
    const float* xr = xin + ((size_t)row << 11);
    float s = 0.f, s2 = 0.f;
    for (int i = threadIdx.x; i < 2048; i += 256) { float v = xr[i]; s += v; s2 += v * v; }
#pragma unroll
    for (int o = 16; o; o >>= 1) { s += __shfl_xor_sync(~0u, s, o); s2 += __shfl_xor_sync(~0u, s2, o); }
    int w = threadIdx.x >> 5;
    if ((threadIdx.x & 31) == 0) { sbuf[w] = s; sbuf[8 + w] = s2; }
    __syncthreads();
    if (threadIdx.x == 0) {
        float S = 0.f, S2 = 0.f;
#pragma unroll
        for (int i = 0; i < 8; i++) { S += sbuf[i]; S2 += sbuf[8 + i]; }
        float m = S * (1.f / 2048.f);
        float var = S2 * (1.f / 2048.f) - m * m;
        g_mu[row] = m;
        g_rs[row] = rsqrtf(var + 1e-5f);
    }
}

// ===================== time-mix prep (LN1 + shift + mixes) =====================
__global__ void tm_prep_k(const float* __restrict__ xin,
                          const float* __restrict__ lnw, const float* __restrict__ lnb,
                          const float* __restrict__ mk, const float* __restrict__ mv,
                          const float* __restrict__ mr)
{
    int i4 = blockIdx.x * 256 + threadIdx.x;
    int row = i4 >> 9;
    int c4 = (i4 & 511) << 2;
    int t = row & 2047;
    size_t gi = ((size_t)row << 11) + c4;

    float xa[4]; *(float4*)xa = *(const float4*)(xin + gi);
    float m = g_mu[row], r_ = g_rs[row];
    float xsa[4] = {0.f, 0.f, 0.f, 0.f};
    float ms = 0.f, rss = 0.f;
    if (t) { *(float4*)xsa = *(const float4*)(xin + gi - 2048); ms = g_mu[row - 1]; rss = g_rs[row - 1]; }

    float ak[4], av[4], ar[4];
#pragma unroll
    for (int j = 0; j < 4; j++) {
        int c = c4 + j;
        float lw = lnw[c], lb = lnb[c];
        float lx  = (xa[j] - m) * r_ * lw + lb;
        float lxs = t ? (xsa[j] - ms) * rss * lw + lb : 0.f;
        float k_ = mk[c]; ak[j] = lx * k_ + lxs * (1.f - k_);
        float v_ = mv[c]; av[j] = lx * v_ + lxs * (1.f - v_);
        float q_ = mr[c]; ar[j] = sigmoidf_(lx * q_ + lxs * (1.f - q_));
    }
    *(__half2*)(g_h0 + gi)     = __floats2half2_rn(ak[0], ak[1]);
    *(__half2*)(g_h0 + gi + 2) = __floats2half2_rn(ak[2], ak[3]);
    *(__half2*)(g_h1 + gi)     = __floats2half2_rn(av[0], av[1]);
    *(__half2*)(g_h1 + gi + 2) = __floats2half2_rn(av[2], av[3]);
    *(__half2*)(g_h2 + gi)     = __floats2half2_rn(ar[0], ar[1]);
    *(__half2*)(g_h2 + gi + 2) = __floats2half2_rn(ar[2], ar[3]);
}

// ===================== channel-mix prep (LN2 + shift + mixes) =====================
__global__ void cm_prep_k(const float* __restrict__ xin,
                          const float* __restrict__ lnw, const float* __restrict__ lnb,
                          const float* __restrict__ mk, const float* __restrict__ mr)
{
    int i4 = blockIdx.x * 256 + threadIdx.x;
    int row = i4 >> 9;
    int c4 = (i4 & 511) << 2;
    int t = row & 2047;
    size_t gi = ((size_t)row << 11) + c4;

    float xa[4]; *(float4*)xa = *(const float4*)(xin + gi);
    float m = g_mu[row], r_ = g_rs[row];
    float xsa[4] = {0.f, 0.f, 0.f, 0.f};
    float ms = 0.f, rss = 0.f;
    if (t) { *(float4*)xsa = *(const float4*)(xin + gi - 2048); ms = g_mu[row - 1]; rss = g_rs[row - 1]; }

    float ak[4], ar[4];
#pragma unroll
    for (int j = 0; j < 4; j++) {
        int c = c4 + j;
        float lw = lnw[c], lb = lnb[c];
        float lx  = (xa[j] - m) * r_ * lw + lb;
        float lxs = t ? (xsa[j] - ms) * rss * lw + lb : 0.f;
        float k_ = mk[c]; ak[j] = lx * k_ + lxs * (1.f - k_);
        float q_ = mr[c]; ar[j] = lx * q_ + lxs * (1.f - q_);
    }
    *(__half2*)(g_h1 + gi)     = __floats2half2_rn(ak[0], ak[1]);
    *(__half2*)(g_h1 + gi + 2) = __floats2half2_rn(ak[2], ak[3]);
    *(__half2*)(g_h2 + gi)     = __floats2half2_rn(ar[0], ar[1]);
    *(__half2*)(g_h2 + gi + 2) = __floats2half2_rn(ar[2], ar[3]);
}

// ===================== chunked parallel WKV scan =====================
__global__ void scan_k(const float* __restrict__ u, const float* __restrict__ w)
{
    int gidx = blockIdx.x * 256 + threadIdx.x;   // B * 16 * 2048 total
    int c = gidx & 2047;
    int bc = gidx >> 11;
    int chunk = bc & 15, b = bc >> 4;
    float uu = u[c], ww = w[c];
    int cs = chunk << 7;
    int t0 = cs - 64; if (t0 < 0) t0 = 0;

    const float* kp = g_k + (((size_t)(b * 2048 + t0)) << 11) + c;
    const float* vp = g_v + (((size_t)(b * 2048 + t0)) << 11) + c;
    float a = 0.f, bsum = 0.f;
    for (int t = t0; t < cs; ++t) {
        float kt = *kp, vt = *vp; kp += 2048; vp += 2048;
        float q = fmaxf(uu + kt, ww);
        float e1 = __expf(-ww - q);
        float e2 = __expf(uu + kt - q);
        a = fmaf(e1, a, e2 * vt);
        bsum = fmaf(e1, bsum, e2);
    }
    const __half* rp = g_h3 + (((size_t)(b * 2048 + cs)) << 11) + c;
    __half* op = g_h0 + (((size_t)(b * 2048 + cs)) << 11) + c;
    for (int t = 0; t < 128; ++t) {
        float kt = *kp, vt = *vp; kp += 2048; vp += 2048;
        float q = fmaxf(uu + kt, ww);
        float e1 = __expf(-ww - q);
        float e2 = __expf(uu + kt - q);
        a = fmaf(e1, a, e2 * vt);
        bsum = fmaf(e1, bsum, e2);
        float rr = __half2float(*rp); rp += 2048;
        *op = __float2half(a / bsum * rr); op += 2048;
    }
}

// ===================== launch =====================
extern "C" void kernel_launch(void* const* d_in, const int* in_sizes, int n_in,
                              void* d_out, int out_size)
{
    const float* x     = (const float*)d_in[0];
    const float* ln1w  = (const float*)d_in[1];
    const float* ln1b  = (const float*)d_in[2];
    const float* ln2w  = (const float*)d_in[3];
    const float* ln2b  = (const float*)d_in[4];
    const float* tmu   = (const float*)d_in[5];
    const float* tmw   = (const float*)d_in[6];
    const float* tmk   = (const float*)d_in[7];
    const float* tmv   = (const float*)d_in[8];
    const float* tmr   = (const float*)d_in[9];
    const float* tmWk  = (const float*)d_in[10];
    const float* tmWv  = (const float*)d_in[11];
    const float* tmWr  = (const float*)d_in[12];
    const float* tmWo  = (const float*)d_in[13];
    const float* tmbo  = (const float*)d_in[14];
    const float* cmk   = (const float*)d_in[15];
    const float* cmr   = (const float*)d_in[16];
    const float* cmWk  = (const float*)d_in[17];
    const float* cmWv  = (const float*)d_in[18];
    const float* cmWr  = (const float*)d_in[19];
    float* out = (float*)d_out;

    __half *h0, *h1, *h2, *h3, *wh;
    float *kf, *vf, *x1f;
    cudaGetSymbolAddress((void**)&h0, g_h0);
    cudaGetSymbolAddress((void**)&h1, g_h1);
    cudaGetSymbolAddress((void**)&h2, g_h2);
    cudaGetSymbolAddress((void**)&h3, g_h3);
    cudaGetSymbolAddress((void**)&wh, g_Wh);
    cudaGetSymbolAddress((void**)&kf, g_k);
    cudaGetSymbolAddress((void**)&vf, g_v);
    cudaGetSymbolAddress((void**)&x1f, g_x1);

    cudaFuncSetAttribute(gemm_k<0>, cudaFuncAttributeMaxDynamicSharedMemorySize, GSM);
    cudaFuncSetAttribute(gemm_k<1>, cudaFuncAttributeMaxDynamicSharedMemorySize, GSM);
    cudaFuncSetAttribute(gemm_k<2>, cudaFuncAttributeMaxDynamicSharedMemorySize, GSM);
    cudaFuncSetAttribute(gemm_k<3>, cudaFuncAttributeMaxDynamicSharedMemorySize, GSM);
    cudaFuncSetAttribute(gemm_k<4>, cudaFuncAttributeMaxDynamicSharedMemorySize, GSM);
    cudaFuncSetAttribute(gemm_k<5>, cudaFuncAttributeMaxDynamicSharedMemorySize, GSM);

    dim3 gg(16, 128);   // x: N/128, y: M/128

    // tcgen05 capability self-test (sets g_flag)
    selftest_k<<<1, 256>>>();

    // weights fp32 -> fp16 (order: Wk, Wv, Wr, Wo, cmWk, cmWv, cmWr)
    wconv_k<<<(7 * DD / 4) / 256, 256>>>(tmWk, tmWv, tmWr, tmWo, cmWk, cmWv, cmWr);

    // LN1 stats + time-mix prep
    ln_stats_k<<<Mrows, 256>>>(x);
    tm_prep_k<<<(Mrows * (Dd / 4)) / 256, 256>>>(x, ln1w, ln1b, tmk, tmv, tmr);

    // k, v (fp32 for the scan), r = sigmoid(mix) @ Wr.T (fp16, NO epilogue sigmoid)
    gemm_k<0><<<gg, 256, GSM>>>(h0, wh + 0 * DDll, kf, nullptr, nullptr, nullptr, nullptr);
    gemm_k<0><<<gg, 256, GSM>>>(h1, wh + 1 * DDll, vf, nullptr, nullptr, nullptr, nullptr);
    gemm_k<1><<<gg, 256, GSM>>>(h2, wh + 2 * DDll, nullptr, h3, nullptr, nullptr, nullptr);

    // wkv * r  -> h0 (fp16)
    scan_k<<<(Bb * 16 * Dd) / 256, 256>>>(tmu, tmw);

    // x1 = x + (wkv*r) @ Wo.T + bo
    gemm_k<4><<<gg, 256, GSM>>>(h0, wh + 3 * DDll, x1f, nullptr, tmbo, x, nullptr);

    // LN2 stats + channel-mix prep
    ln_stats_k<<<Mrows, 256>>>(x1f);
    cm_prep_k<<<(Mrows * (Dd / 4)) / 256, 256>>>(x1f, ln2w, ln2b, cmk, cmr);

    // kcm = relu(mix @ cmWk.T)^2 (fp16) ; rcm = sigmoid(mix @ cmWr.T) (fp16)
    gemm_k<3><<<gg, 256, GSM>>>(h1, wh + 4 * DDll, nullptr, h0, nullptr, nullptr, nullptr);
    gemm_k<2><<<gg, 256, GSM>>>(h2, wh + 6 * DDll, nullptr, h3, nullptr, nullptr, nullptr);

    // out = x1 + rcm * (kcm @ cmWv.T)
    gemm_k<5><<<gg, 256, GSM>>>(h0, wh + 5 * DDll, out, nullptr, nullptr, x1f, h3);
}